// round 7
// baseline (speedup 1.0000x reference)
#include <cuda_runtime.h>
#include <math.h>

#define NJ 17
#define ND 128
#define NH 2
#define NDH 64
#define NITER 4
#define LNEPS 1e-5f
#define NTHREADS 256
#define XSTR 20          // padded row stride for transposed xn tile (80B: 16B-aligned rows)

typedef unsigned long long ull;

// ---- fixed 17-node skeleton adjacency (incl. self), flattened neighbor lists ----
__constant__ int c_nbr_off[18] = {0,4,7,10,12,15,18,20,23,28,31,33,36,39,41,44,47,49};
__constant__ int c_nbr[49] = {
    0,1,4,7,  0,1,2,  1,2,3,  2,3,  0,4,5,  4,5,6,  5,6,  0,7,8,
    7,8,9,11,14,  8,9,10,  9,10,  8,11,12,  11,12,13,  12,13,
    8,14,15,  14,15,16,  15,16};

// Lane-replicated weight copies: g_w?dup[k*N + n] = (w[k][n], w[k][n]).
// Filled by pack_weights_kernel each launch (deterministic). This removes the
// per-k pack2() MOVs from the GEMM hot loop — FFMA2 reads the pair via LDG.64.
__device__ float2 g_w1dup[ND * 2*ND];
__device__ float2 g_w2dup[ND * 2*ND];
__device__ float2 g_vwdup[ND * ND];

__global__ void pack_weights_kernel(const float* __restrict__ w1,
                                    const float* __restrict__ w2,
                                    const float* __restrict__ vw) {
    const int i = blockIdx.x * blockDim.x + threadIdx.x;
    if (i < ND * 2*ND) {
        float v = w1[i]; g_w1dup[i] = make_float2(v, v);
        v = w2[i];       g_w2dup[i] = make_float2(v, v);
    }
    if (i < ND * ND) {
        const float v = vw[i]; g_vwdup[i] = make_float2(v, v);
    }
}

// float4/LDS.128 members must be 16B aligned (R1 lesson).
struct SmemLayout {
    alignas(16) float xs[NJ][ND];
    alignas(16) float x0s[NJ][ND];
    alignas(16) float xnT[ND][XSTR];   // row stride 80B (16-mult)
    alignas(16) float Ls[NJ][2*ND];
    alignas(16) float Rs[NJ][2*ND];
    alignas(16) float Vs[NJ][ND];
    alignas(16) float skipv[NJ];
    alignas(16) float lnG[ND];
    alignas(16) float lnB[ND];
    alignas(16) float aW[ND];
    alignas(16) float psW[ND];
    alignas(16) float vbs[ND];
    alignas(16) float b1s[2*ND];
    alignas(16) float b2s[2*ND];
    alignas(16) float alpha_b0;
    float ps_b0;
};

__device__ __forceinline__ float wredsum(float v) {
    #pragma unroll
    for (int o = 16; o; o >>= 1) v += __shfl_xor_sync(0xffffffffu, v, o);
    return v;
}

// ---- packed fp32x2 helpers (sm_103a FFMA2 path) ----
__device__ __forceinline__ void ffma2(ull& d, ull a, ull b) {
    asm("fma.rn.f32x2 %0, %1, %2, %0;" : "+l"(d) : "l"(a), "l"(b));
}
__device__ __forceinline__ float2 unpack2(ull v) {
    float lo, hi; asm("mov.b64 {%0, %1}, %2;" : "=f"(lo), "=f"(hi) : "l"(v));
    return make_float2(lo, hi);
}

__global__ void __launch_bounds__(NTHREADS, 2)
spatial_appnp_kernel(
    const float* __restrict__ x,
    const float* __restrict__ og,  const float* __restrict__ ob,
    const float* __restrict__ lg,  const float* __restrict__ lb,
    const float* __restrict__ aw,  const float* __restrict__ ab,
    const float* __restrict__ b1,  const float* __restrict__ b2,
    const float* __restrict__ psw, const float* __restrict__ psb,
    const float* __restrict__ vb,
    float* __restrict__ out)
{
    extern __shared__ float smem_raw[];
    SmemLayout* sm = reinterpret_cast<SmemLayout*>(smem_raw);

    const int tid  = threadIdx.x;
    const int lane = tid & 31;
    const int wid  = tid >> 5;
    const int tile = blockIdx.x;
    const float* xg = x + (size_t)tile * NJ * ND;

    // ---- parameter staging (consumed after the first __syncthreads) ----
    for (int i = tid; i < ND; i += NTHREADS) {
        sm->lnG[i] = lg[i]; sm->lnB[i] = lb[i];
        sm->aW[i]  = aw[i]; sm->psW[i] = psw[i];
        sm->vbs[i] = vb[i];
    }
    for (int i = tid; i < 2*ND; i += NTHREADS) { sm->b1s[i] = b1[i]; sm->b2s[i] = b2[i]; }
    if (tid == 0) { sm->alpha_b0 = ab[0]; sm->ps_b0 = psb[0]; }

    // ---- outer LayerNorm: x -> xs, x0s (interleaved channels, one-pass var) ----
    for (int j = wid; j < NJ; j += 8) {
        const float v0 = xg[j*ND + lane];
        const float v1 = xg[j*ND + lane + 32];
        const float v2 = xg[j*ND + lane + 64];
        const float v3 = xg[j*ND + lane + 96];
        float s1 = v0+v1+v2+v3;
        float s2 = v0*v0+v1*v1+v2*v2+v3*v3;
        #pragma unroll
        for (int o = 16; o; o >>= 1) {
            s1 += __shfl_xor_sync(0xffffffffu, s1, o);
            s2 += __shfl_xor_sync(0xffffffffu, s2, o);
        }
        const float mean = s1 * (1.0f/ND);
        const float var  = s2 * (1.0f/ND) - mean*mean;
        const float rs = rsqrtf(var + LNEPS);
        const float y0 = (v0-mean)*rs*og[lane     ] + ob[lane     ];
        const float y1 = (v1-mean)*rs*og[lane + 32] + ob[lane + 32];
        const float y2 = (v2-mean)*rs*og[lane + 64] + ob[lane + 64];
        const float y3 = (v3-mean)*rs*og[lane + 96] + ob[lane + 96];
        sm->xs[j][lane     ] = y0;  sm->x0s[j][lane     ] = y0;
        sm->xs[j][lane + 32] = y1;  sm->x0s[j][lane + 32] = y1;
        sm->xs[j][lane + 64] = y2;  sm->x0s[j][lane + 64] = y2;
        sm->xs[j][lane + 96] = y3;  sm->x0s[j][lane + 96] = y3;
    }
    __syncthreads();

    for (int it = 0; it < NITER; ++it) {
        // ---- Phase 1: inner LN(xs) -> xnT (transposed), skip gate ----
        for (int j = wid; j < NJ; j += 8) {
            const float v0 = sm->xs[j][lane];
            const float v1 = sm->xs[j][lane + 32];
            const float v2 = sm->xs[j][lane + 64];
            const float v3 = sm->xs[j][lane + 96];
            float s1 = v0+v1+v2+v3;
            float s2 = v0*v0+v1*v1+v2*v2+v3*v3;
            #pragma unroll
            for (int o = 16; o; o >>= 1) {
                s1 += __shfl_xor_sync(0xffffffffu, s1, o);
                s2 += __shfl_xor_sync(0xffffffffu, s2, o);
            }
            const float mean = s1 * (1.0f/ND);
            const float var  = s2 * (1.0f/ND) - mean*mean;
            const float rs = rsqrtf(var + LNEPS);
            const float y0 = (v0-mean)*rs*sm->lnG[lane     ] + sm->lnB[lane     ];
            const float y1 = (v1-mean)*rs*sm->lnG[lane + 32] + sm->lnB[lane + 32];
            const float y2 = (v2-mean)*rs*sm->lnG[lane + 64] + sm->lnB[lane + 64];
            const float y3 = (v3-mean)*rs*sm->lnG[lane + 96] + sm->lnB[lane + 96];
            float dot = y0*sm->aW[lane] + y1*sm->aW[lane+32]
                      + y2*sm->aW[lane+64] + y3*sm->aW[lane+96];
            dot = wredsum(dot);
            if (lane == 0)
                sm->skipv[j] = 1.0f / (1.0f + expf(-(dot + sm->alpha_b0)));
            sm->xnT[lane     ][j] = y0;
            sm->xnT[lane + 32][j] = y1;
            sm->xnT[lane + 64][j] = y2;
            sm->xnT[lane + 96][j] = y3;
        }
        __syncthreads();

        // ---- Phase 2+3 fused: L = xn@w1+b1, R = xn@w2+b2, V = xn@v_w+v_b ----
        // Weights arrive lane-replicated via LDG.64 (no pack2 MOVs in the loop).
        {
            const int n  = tid;
            const int nv = tid & 127;
            ull accL[8], accR[8], accV[4];
            float aL16 = 0.f, aR16 = 0.f, aV16 = 0.f;
            #pragma unroll
            for (int q = 0; q < 8; ++q) { accL[q] = 0ull; accR[q] = 0ull; }
            #pragma unroll
            for (int q = 0; q < 4; ++q) accV[q] = 0ull;

            const ull* w1p = reinterpret_cast<const ull*>(g_w1dup) + n;
            const ull* w2p = reinterpret_cast<const ull*>(g_w2dup) + n;
            const ull* vwp = reinterpret_cast<const ull*>(g_vwdup) + nv;

            if (tid < 128) {
                #pragma unroll 4
                for (int k = 0; k < ND; ++k) {
                    const ull waa = w1p[k*(2*ND)];
                    const ull wbb = w2p[k*(2*ND)];
                    const ull wvv = vwp[k*ND];
                    const ulonglong2* xr = reinterpret_cast<const ulonglong2*>(&sm->xnT[k][0]);
                    const ulonglong2 pA = xr[0];
                    const ulonglong2 pB = xr[1];
                    const ulonglong2 pC = xr[2];
                    const ulonglong2 pD = xr[3];
                    const float x16 = sm->xnT[k][16];
                    ffma2(accL[0], pA.x, waa); ffma2(accR[0], pA.x, wbb);
                    ffma2(accL[1], pA.y, waa); ffma2(accR[1], pA.y, wbb);
                    ffma2(accL[2], pB.x, waa); ffma2(accR[2], pB.x, wbb);
                    ffma2(accL[3], pB.y, waa); ffma2(accR[3], pB.y, wbb);
                    ffma2(accL[4], pC.x, waa); ffma2(accR[4], pC.x, wbb);
                    ffma2(accL[5], pC.y, waa); ffma2(accR[5], pC.y, wbb);
                    ffma2(accL[6], pD.x, waa); ffma2(accR[6], pD.x, wbb);
                    ffma2(accL[7], pD.y, waa); ffma2(accR[7], pD.y, wbb);
                    aL16 = fmaf(x16, unpack2(waa).x, aL16);
                    aR16 = fmaf(x16, unpack2(wbb).x, aR16);
                    ffma2(accV[0], pA.x, wvv); ffma2(accV[1], pA.y, wvv);
                    ffma2(accV[2], pB.x, wvv); ffma2(accV[3], pB.y, wvv);
                    aV16 = fmaf(x16, unpack2(wvv).x, aV16);
                }
            } else {
                #pragma unroll 4
                for (int k = 0; k < ND; ++k) {
                    const ull waa = w1p[k*(2*ND)];
                    const ull wbb = w2p[k*(2*ND)];
                    const ull wvv = vwp[k*ND];
                    const ulonglong2* xr = reinterpret_cast<const ulonglong2*>(&sm->xnT[k][0]);
                    const ulonglong2 pA = xr[0];
                    const ulonglong2 pB = xr[1];
                    const ulonglong2 pC = xr[2];
                    const ulonglong2 pD = xr[3];
                    const float x16 = sm->xnT[k][16];
                    ffma2(accL[0], pA.x, waa); ffma2(accR[0], pA.x, wbb);
                    ffma2(accL[1], pA.y, waa); ffma2(accR[1], pA.y, wbb);
                    ffma2(accL[2], pB.x, waa); ffma2(accR[2], pB.x, wbb);
                    ffma2(accL[3], pB.y, waa); ffma2(accR[3], pB.y, wbb);
                    ffma2(accL[4], pC.x, waa); ffma2(accR[4], pC.x, wbb);
                    ffma2(accL[5], pC.y, waa); ffma2(accR[5], pC.y, wbb);
                    ffma2(accL[6], pD.x, waa); ffma2(accR[6], pD.x, wbb);
                    ffma2(accL[7], pD.y, waa); ffma2(accR[7], pD.y, wbb);
                    aL16 = fmaf(x16, unpack2(waa).x, aL16);
                    aR16 = fmaf(x16, unpack2(wbb).x, aR16);
                    ffma2(accV[0], pC.x, wvv); ffma2(accV[1], pC.y, wvv);
                    ffma2(accV[2], pD.x, wvv); ffma2(accV[3], pD.y, wvv);
                }
            }

            const float bb1 = sm->b1s[n], bb2 = sm->b2s[n];
            #pragma unroll
            for (int q = 0; q < 8; ++q) {
                const float2 l2 = unpack2(accL[q]);
                const float2 r2 = unpack2(accR[q]);
                sm->Ls[2*q  ][n] = l2.x + bb1;
                sm->Ls[2*q+1][n] = l2.y + bb1;
                sm->Rs[2*q  ][n] = r2.x + bb2;
                sm->Rs[2*q+1][n] = r2.y + bb2;
            }
            sm->Ls[16][n] = aL16 + bb1;
            sm->Rs[16][n] = aR16 + bb2;

            const float bbv = sm->vbs[nv];
            if (tid < 128) {
                #pragma unroll
                for (int q = 0; q < 4; ++q) {
                    const float2 v2 = unpack2(accV[q]);
                    sm->Vs[2*q  ][nv] = v2.x + bbv;
                    sm->Vs[2*q+1][nv] = v2.y + bbv;
                }
                sm->Vs[16][nv] = aV16 + bbv;
            } else {
                #pragma unroll
                for (int q = 0; q < 4; ++q) {
                    const float2 v2 = unpack2(accV[q]);
                    sm->Vs[8+2*q  ][nv] = v2.x + bbv;
                    sm->Vs[8+2*q+1][nv] = v2.y + bbv;
                }
            }
        }
        __syncthreads();

        // ---- Phase 4+5 fused: per-(h,i) edge scores + softmax + aggregate
        //      + gelu + skip combine -> xs ----
        for (int u = wid; u < 2*NJ; u += 8) {
            const int h  = (u >= NJ) ? 1 : 0;
            const int i  = u - h*NJ;
            const int o0 = c_nbr_off[i];
            const int deg = c_nbr_off[i+1] - o0;

            const float4 lv = reinterpret_cast<const float4*>(&sm->Ls[i][h*ND])[lane];
            const float4 pw = reinterpret_cast<const float4*>(sm->psW)[lane];

            float sc[5]; int nb[5];
            #pragma unroll
            for (int d = 0; d < 5; ++d) {
                const bool valid = d < deg;
                nb[d] = valid ? c_nbr[o0 + d] : i;
                const float4 rv = reinterpret_cast<const float4*>(&sm->Rs[nb[d]][h*ND])[lane];
                float z, acc;
                z = lv.x + rv.x; z = fmaxf(z, 0.2f*z); acc  = z*pw.x;
                z = lv.y + rv.y; z = fmaxf(z, 0.2f*z); acc += z*pw.y;
                z = lv.z + rv.z; z = fmaxf(z, 0.2f*z); acc += z*pw.z;
                z = lv.w + rv.w; z = fmaxf(z, 0.2f*z); acc += z*pw.w;
                sc[d] = acc;
            }
            // 5 interleaved warp reductions (chains overlap)
            #pragma unroll
            for (int o = 16; o; o >>= 1) {
                sc[0] += __shfl_xor_sync(0xffffffffu, sc[0], o);
                sc[1] += __shfl_xor_sync(0xffffffffu, sc[1], o);
                sc[2] += __shfl_xor_sync(0xffffffffu, sc[2], o);
                sc[3] += __shfl_xor_sync(0xffffffffu, sc[3], o);
                sc[4] += __shfl_xor_sync(0xffffffffu, sc[4], o);
            }
            const float psb0 = sm->ps_b0;
            #pragma unroll
            for (int d = 0; d < 5; ++d)
                sc[d] = (d < deg) ? sc[d] + psb0 : -1e30f;

            float m = sc[0];
            #pragma unroll
            for (int d = 1; d < 5; ++d) m = fmaxf(m, sc[d]);
            float den = 0.f;
            #pragma unroll
            for (int d = 0; d < 5; ++d) { sc[d] = expf(sc[d] - m); den += sc[d]; }
            const float inv = 1.0f / den;

            float acc0 = 0.f, acc1 = 0.f;
            #pragma unroll
            for (int d = 0; d < 5; ++d) {
                const float* vr = &sm->Vs[nb[d]][h*NDH];
                acc0 = fmaf(sc[d], vr[lane],      acc0);
                acc1 = fmaf(sc[d], vr[lane + 32], acc1);
            }
            acc0 *= inv; acc1 *= inv;
            acc0 = 0.5f*acc0*(1.0f + erff(acc0*0.70710678118654752f));
            acc1 = 0.5f*acc1*(1.0f + erff(acc1*0.70710678118654752f));
            const float sk = sm->skipv[i];
            const int c0 = h*NDH + lane;
            sm->xs[i][c0]      = (1.0f - sk)*acc0 + sk*sm->x0s[i][c0];
            sm->xs[i][c0+32]   = (1.0f - sk)*acc1 + sk*sm->x0s[i][c0+32];
        }
        __syncthreads();
    }

    // ---- write result ----
    float* og_out = out + (size_t)tile * NJ * ND;
    for (int j = wid; j < NJ; j += 8) {
        reinterpret_cast<float4*>(og_out + j*ND)[lane] =
            reinterpret_cast<const float4*>(sm->xs[j])[lane];
    }
}

extern "C" void kernel_launch(void* const* d_in, const int* in_sizes, int n_in,
                              void* d_out, int out_size) {
    const float* x   = (const float*)d_in[0];
    const float* og  = (const float*)d_in[1];
    const float* ob  = (const float*)d_in[2];
    const float* lg  = (const float*)d_in[3];
    const float* lb  = (const float*)d_in[4];
    const float* aw  = (const float*)d_in[5];
    const float* ab  = (const float*)d_in[6];
    const float* w1  = (const float*)d_in[7];
    const float* b1  = (const float*)d_in[8];
    const float* w2  = (const float*)d_in[9];
    const float* b2  = (const float*)d_in[10];
    const float* psw = (const float*)d_in[11];
    const float* psb = (const float*)d_in[12];
    const float* vw  = (const float*)d_in[13];
    const float* vb  = (const float*)d_in[14];

    const int tiles = in_sizes[0] / (NJ * ND);  // 3888

    // stage lane-replicated weights (same stream -> ordered before main kernel)
    pack_weights_kernel<<<(ND*2*ND + 255)/256, 256>>>(w1, w2, vw);

    const size_t smem_bytes = sizeof(SmemLayout);
    cudaFuncSetAttribute(spatial_appnp_kernel,
                         cudaFuncAttributeMaxDynamicSharedMemorySize,
                         (int)smem_bytes);
    spatial_appnp_kernel<<<tiles, NTHREADS, smem_bytes>>>(
        x, og, ob, lg, lb, aw, ab, b1, b2, psw, psb, vb,
        (float*)d_out);
}

// round 9
// speedup vs baseline: 1.0260x; 1.0260x over previous
#include <cuda_runtime.h>
#include <math.h>

#define NJ 17
#define ND 128
#define NH 2
#define NDH 64
#define NITER 4
#define LNEPS 1e-5f
#define NTHREADS 256
#define XSTR 20          // padded row stride for transposed xn tile (80B: 16B-aligned rows)

typedef unsigned long long ull;

// ---- fixed 17-node skeleton adjacency (incl. self), flattened neighbor lists ----
__constant__ int c_nbr_off[18] = {0,4,7,10,12,15,18,20,23,28,31,33,36,39,41,44,47,49};
__constant__ int c_nbr[49] = {
    0,1,4,7,  0,1,2,  1,2,3,  2,3,  0,4,5,  4,5,6,  5,6,  0,7,8,
    7,8,9,11,14,  8,9,10,  9,10,  8,11,12,  11,12,13,  12,13,
    8,14,15,  14,15,16,  15,16};

// float4/LDS.128 members must be 16B aligned (R1 lesson).
struct SmemLayout {
    alignas(16) float xs[NJ][ND];
    alignas(16) float x0s[NJ][ND];
    alignas(16) float xnT[ND][XSTR];   // row stride 80B (16-mult)
    alignas(16) float Ls[NJ][2*ND];
    alignas(16) float Rs[NJ][2*ND];
    alignas(16) float Vs[NJ][ND];
    alignas(16) float skipv[NJ];
    alignas(16) float lnG[ND];
    alignas(16) float lnB[ND];
    alignas(16) float aW[ND];
    alignas(16) float psW[ND];
    alignas(16) float vbs[ND];
    alignas(16) float b1s[2*ND];
    alignas(16) float b2s[2*ND];
    alignas(16) float alpha_b0;
    float ps_b0;
};

__device__ __forceinline__ float wredsum(float v) {
    #pragma unroll
    for (int o = 16; o; o >>= 1) v += __shfl_xor_sync(0xffffffffu, v, o);
    return v;
}

// ---- packed fp32x2 helpers (sm_103a FFMA2 path) ----
__device__ __forceinline__ void ffma2(ull& d, ull a, ull b) {
    asm("fma.rn.f32x2 %0, %1, %2, %0;" : "+l"(d) : "l"(a), "l"(b));
}
__device__ __forceinline__ ull pack2(float lo, float hi) {
    ull r; asm("mov.b64 %0, {%1, %2};" : "=l"(r) : "f"(lo), "f"(hi)); return r;
}
__device__ __forceinline__ float2 unpack2(ull v) {
    float lo, hi; asm("mov.b64 {%0, %1}, %2;" : "=f"(lo), "=f"(hi) : "l"(v));
    return make_float2(lo, hi);
}

__global__ void __launch_bounds__(NTHREADS, 3)
spatial_appnp_kernel(
    const float* __restrict__ x,
    const float* __restrict__ og,  const float* __restrict__ ob,
    const float* __restrict__ lg,  const float* __restrict__ lb,
    const float* __restrict__ aw,  const float* __restrict__ ab,
    const float* __restrict__ w1,  const float* __restrict__ b1,
    const float* __restrict__ w2,  const float* __restrict__ b2,
    const float* __restrict__ psw, const float* __restrict__ psb,
    const float* __restrict__ vw,  const float* __restrict__ vb,
    float* __restrict__ out)
{
    extern __shared__ float smem_raw[];
    SmemLayout* sm = reinterpret_cast<SmemLayout*>(smem_raw);

    const int tid  = threadIdx.x;
    const int lane = tid & 31;
    const int wid  = tid >> 5;
    const int tile = blockIdx.x;
    const float* xg = x + (size_t)tile * NJ * ND;

    // ---- parameter staging (consumed after the first __syncthreads) ----
    for (int i = tid; i < ND; i += NTHREADS) {
        sm->lnG[i] = lg[i]; sm->lnB[i] = lb[i];
        sm->aW[i]  = aw[i]; sm->psW[i] = psw[i];
        sm->vbs[i] = vb[i];
    }
    for (int i = tid; i < 2*ND; i += NTHREADS) { sm->b1s[i] = b1[i]; sm->b2s[i] = b2[i]; }
    if (tid == 0) { sm->alpha_b0 = ab[0]; sm->ps_b0 = psb[0]; }

    // ---- outer LayerNorm: x -> xs, x0s (interleaved channels, one-pass var) ----
    for (int j = wid; j < NJ; j += 8) {
        const float v0 = xg[j*ND + lane];
        const float v1 = xg[j*ND + lane + 32];
        const float v2 = xg[j*ND + lane + 64];
        const float v3 = xg[j*ND + lane + 96];
        float s1 = v0+v1+v2+v3;
        float s2 = v0*v0+v1*v1+v2*v2+v3*v3;
        #pragma unroll
        for (int o = 16; o; o >>= 1) {
            s1 += __shfl_xor_sync(0xffffffffu, s1, o);
            s2 += __shfl_xor_sync(0xffffffffu, s2, o);
        }
        const float mean = s1 * (1.0f/ND);
        const float var  = s2 * (1.0f/ND) - mean*mean;
        const float rs = rsqrtf(var + LNEPS);
        const float y0 = (v0-mean)*rs*og[lane     ] + ob[lane     ];
        const float y1 = (v1-mean)*rs*og[lane + 32] + ob[lane + 32];
        const float y2 = (v2-mean)*rs*og[lane + 64] + ob[lane + 64];
        const float y3 = (v3-mean)*rs*og[lane + 96] + ob[lane + 96];
        sm->xs[j][lane     ] = y0;  sm->x0s[j][lane     ] = y0;
        sm->xs[j][lane + 32] = y1;  sm->x0s[j][lane + 32] = y1;
        sm->xs[j][lane + 64] = y2;  sm->x0s[j][lane + 64] = y2;
        sm->xs[j][lane + 96] = y3;  sm->x0s[j][lane + 96] = y3;
    }
    __syncthreads();

    for (int it = 0; it < NITER; ++it) {
        // ---- Phase 1: inner LN(xs) -> xnT (transposed), skip gate ----
        for (int j = wid; j < NJ; j += 8) {
            const float v0 = sm->xs[j][lane];
            const float v1 = sm->xs[j][lane + 32];
            const float v2 = sm->xs[j][lane + 64];
            const float v3 = sm->xs[j][lane + 96];
            float s1 = v0+v1+v2+v3;
            float s2 = v0*v0+v1*v1+v2*v2+v3*v3;
            #pragma unroll
            for (int o = 16; o; o >>= 1) {
                s1 += __shfl_xor_sync(0xffffffffu, s1, o);
                s2 += __shfl_xor_sync(0xffffffffu, s2, o);
            }
            const float mean = s1 * (1.0f/ND);
            const float var  = s2 * (1.0f/ND) - mean*mean;
            const float rs = rsqrtf(var + LNEPS);
            const float y0 = (v0-mean)*rs*sm->lnG[lane     ] + sm->lnB[lane     ];
            const float y1 = (v1-mean)*rs*sm->lnG[lane + 32] + sm->lnB[lane + 32];
            const float y2 = (v2-mean)*rs*sm->lnG[lane + 64] + sm->lnB[lane + 64];
            const float y3 = (v3-mean)*rs*sm->lnG[lane + 96] + sm->lnB[lane + 96];
            float dot = y0*sm->aW[lane] + y1*sm->aW[lane+32]
                      + y2*sm->aW[lane+64] + y3*sm->aW[lane+96];
            dot = wredsum(dot);
            if (lane == 0)
                sm->skipv[j] = 1.0f / (1.0f + expf(-(dot + sm->alpha_b0)));
            sm->xnT[lane     ][j] = y0;
            sm->xnT[lane + 32][j] = y1;
            sm->xnT[lane + 64][j] = y2;
            sm->xnT[lane + 96][j] = y3;
        }
        __syncthreads();

        // ---- Phase 2a: L = xn@w1+b1, R = xn@w2+b2 (register-lean pass) ----
        {
            const int n = tid;
            ull accL[8], accR[8];
            float aL16 = 0.f, aR16 = 0.f;
            #pragma unroll
            for (int q = 0; q < 8; ++q) { accL[q] = 0ull; accR[q] = 0ull; }

            const float* w1p = w1 + n;
            const float* w2p = w2 + n;

            #pragma unroll 4
            for (int k = 0; k < ND; ++k) {
                const float wa = w1p[k*(2*ND)];
                const float wb = w2p[k*(2*ND)];
                const ull waa = pack2(wa, wa);
                const ull wbb = pack2(wb, wb);
                const ulonglong2* xr = reinterpret_cast<const ulonglong2*>(&sm->xnT[k][0]);
                const ulonglong2 pA = xr[0];
                const ulonglong2 pB = xr[1];
                const ulonglong2 pC = xr[2];
                const ulonglong2 pD = xr[3];
                const float x16 = sm->xnT[k][16];
                ffma2(accL[0], pA.x, waa); ffma2(accR[0], pA.x, wbb);
                ffma2(accL[1], pA.y, waa); ffma2(accR[1], pA.y, wbb);
                ffma2(accL[2], pB.x, waa); ffma2(accR[2], pB.x, wbb);
                ffma2(accL[3], pB.y, waa); ffma2(accR[3], pB.y, wbb);
                ffma2(accL[4], pC.x, waa); ffma2(accR[4], pC.x, wbb);
                ffma2(accL[5], pC.y, waa); ffma2(accR[5], pC.y, wbb);
                ffma2(accL[6], pD.x, waa); ffma2(accR[6], pD.x, wbb);
                ffma2(accL[7], pD.y, waa); ffma2(accR[7], pD.y, wbb);
                aL16 = fmaf(x16, wa, aL16);
                aR16 = fmaf(x16, wb, aR16);
            }

            const float bb1 = sm->b1s[n], bb2 = sm->b2s[n];
            #pragma unroll
            for (int q = 0; q < 8; ++q) {
                const float2 l2 = unpack2(accL[q]);
                const float2 r2 = unpack2(accR[q]);
                sm->Ls[2*q  ][n] = l2.x + bb1;
                sm->Ls[2*q+1][n] = l2.y + bb1;
                sm->Rs[2*q  ][n] = r2.x + bb2;
                sm->Rs[2*q+1][n] = r2.y + bb2;
            }
            sm->Ls[16][n] = aL16 + bb1;
            sm->Rs[16][n] = aR16 + bb2;
        }

        // ---- Phase 2b: V = xn@v_w + v_b (second register-lean pass) ----
        {
            const int nv = tid & 127;
            ull accV[4];
            float aV16 = 0.f;
            #pragma unroll
            for (int q = 0; q < 4; ++q) accV[q] = 0ull;
            const float* vwp = vw + nv;

            if (tid < 128) {
                #pragma unroll 4
                for (int k = 0; k < ND; ++k) {
                    const float wv = vwp[k*ND];
                    const ull wvv = pack2(wv, wv);
                    const ulonglong2* xr = reinterpret_cast<const ulonglong2*>(&sm->xnT[k][0]);
                    const ulonglong2 pA = xr[0];
                    const ulonglong2 pB = xr[1];
                    const float x16 = sm->xnT[k][16];
                    ffma2(accV[0], pA.x, wvv); ffma2(accV[1], pA.y, wvv);
                    ffma2(accV[2], pB.x, wvv); ffma2(accV[3], pB.y, wvv);
                    aV16 = fmaf(x16, wv, aV16);
                }
                const float bbv = sm->vbs[nv];
                #pragma unroll
                for (int q = 0; q < 4; ++q) {
                    const float2 v2 = unpack2(accV[q]);
                    sm->Vs[2*q  ][nv] = v2.x + bbv;
                    sm->Vs[2*q+1][nv] = v2.y + bbv;
                }
                sm->Vs[16][nv] = aV16 + bbv;
            } else {
                #pragma unroll 4
                for (int k = 0; k < ND; ++k) {
                    const float wv = vwp[k*ND];
                    const ull wvv = pack2(wv, wv);
                    const ulonglong2* xr = reinterpret_cast<const ulonglong2*>(&sm->xnT[k][0]);
                    const ulonglong2 pC = xr[2];
                    const ulonglong2 pD = xr[3];
                    ffma2(accV[0], pC.x, wvv); ffma2(accV[1], pC.y, wvv);
                    ffma2(accV[2], pD.x, wvv); ffma2(accV[3], pD.y, wvv);
                }
                const float bbv = sm->vbs[nv];
                #pragma unroll
                for (int q = 0; q < 4; ++q) {
                    const float2 v2 = unpack2(accV[q]);
                    sm->Vs[8+2*q  ][nv] = v2.x + bbv;
                    sm->Vs[8+2*q+1][nv] = v2.y + bbv;
                }
            }
        }
        __syncthreads();

        // ---- Phase 4+5 fused: per-(h,i) edge scores + softmax + aggregate
        //      + gelu + skip combine -> xs ----
        for (int u = wid; u < 2*NJ; u += 8) {
            const int h  = (u >= NJ) ? 1 : 0;
            const int i  = u - h*NJ;
            const int o0 = c_nbr_off[i];
            const int deg = c_nbr_off[i+1] - o0;

            const float4 lv = reinterpret_cast<const float4*>(&sm->Ls[i][h*ND])[lane];
            const float4 pw = reinterpret_cast<const float4*>(sm->psW)[lane];

            float sc[5]; int nb[5];
            #pragma unroll
            for (int d = 0; d < 5; ++d) {
                const bool valid = d < deg;
                nb[d] = valid ? c_nbr[o0 + d] : i;
                const float4 rv = reinterpret_cast<const float4*>(&sm->Rs[nb[d]][h*ND])[lane];
                float z, acc;
                z = lv.x + rv.x; z = fmaxf(z, 0.2f*z); acc  = z*pw.x;
                z = lv.y + rv.y; z = fmaxf(z, 0.2f*z); acc += z*pw.y;
                z = lv.z + rv.z; z = fmaxf(z, 0.2f*z); acc += z*pw.z;
                z = lv.w + rv.w; z = fmaxf(z, 0.2f*z); acc += z*pw.w;
                sc[d] = acc;
            }
            // 5 interleaved warp reductions (chains overlap)
            #pragma unroll
            for (int o = 16; o; o >>= 1) {
                sc[0] += __shfl_xor_sync(0xffffffffu, sc[0], o);
                sc[1] += __shfl_xor_sync(0xffffffffu, sc[1], o);
                sc[2] += __shfl_xor_sync(0xffffffffu, sc[2], o);
                sc[3] += __shfl_xor_sync(0xffffffffu, sc[3], o);
                sc[4] += __shfl_xor_sync(0xffffffffu, sc[4], o);
            }
            const float psb0 = sm->ps_b0;
            #pragma unroll
            for (int d = 0; d < 5; ++d)
                sc[d] = (d < deg) ? sc[d] + psb0 : -1e30f;

            float m = sc[0];
            #pragma unroll
            for (int d = 1; d < 5; ++d) m = fmaxf(m, sc[d]);
            float den = 0.f;
            #pragma unroll
            for (int d = 0; d < 5; ++d) { sc[d] = expf(sc[d] - m); den += sc[d]; }
            const float inv = 1.0f / den;

            float acc0 = 0.f, acc1 = 0.f;
            #pragma unroll
            for (int d = 0; d < 5; ++d) {
                const float* vr = &sm->Vs[nb[d]][h*NDH];
                acc0 = fmaf(sc[d], vr[lane],      acc0);
                acc1 = fmaf(sc[d], vr[lane + 32], acc1);
            }
            acc0 *= inv; acc1 *= inv;
            acc0 = 0.5f*acc0*(1.0f + erff(acc0*0.70710678118654752f));
            acc1 = 0.5f*acc1*(1.0f + erff(acc1*0.70710678118654752f));
            const float sk = sm->skipv[i];
            const int c0 = h*NDH + lane;
            sm->xs[i][c0]      = (1.0f - sk)*acc0 + sk*sm->x0s[i][c0];
            sm->xs[i][c0+32]   = (1.0f - sk)*acc1 + sk*sm->x0s[i][c0+32];
        }
        __syncthreads();
    }

    // ---- write result ----
    float* og_out = out + (size_t)tile * NJ * ND;
    for (int j = wid; j < NJ; j += 8) {
        reinterpret_cast<float4*>(og_out + j*ND)[lane] =
            reinterpret_cast<const float4*>(sm->xs[j])[lane];
    }
}

extern "C" void kernel_launch(void* const* d_in, const int* in_sizes, int n_in,
                              void* d_out, int out_size) {
    const float* x   = (const float*)d_in[0];
    const float* og  = (const float*)d_in[1];
    const float* ob  = (const float*)d_in[2];
    const float* lg  = (const float*)d_in[3];
    const float* lb  = (const float*)d_in[4];
    const float* aw  = (const float*)d_in[5];
    const float* ab  = (const float*)d_in[6];
    const float* w1  = (const float*)d_in[7];
    const float* b1  = (const float*)d_in[8];
    const float* w2  = (const float*)d_in[9];
    const float* b2  = (const float*)d_in[10];
    const float* psw = (const float*)d_in[11];
    const float* psb = (const float*)d_in[12];
    const float* vw  = (const float*)d_in[13];
    const float* vb  = (const float*)d_in[14];

    const int tiles = in_sizes[0] / (NJ * ND);  // 3888
    const size_t smem_bytes = sizeof(SmemLayout);
    cudaFuncSetAttribute(spatial_appnp_kernel,
                         cudaFuncAttributeMaxDynamicSharedMemorySize,
                         (int)smem_bytes);
    spatial_appnp_kernel<<<tiles, NTHREADS, smem_bytes>>>(
        x, og, ob, lg, lb, aw, ab, w1, b1, w2, b2, psw, psb, vw, vb,
        (float*)d_out);
}

// round 10
// speedup vs baseline: 1.1008x; 1.0728x over previous
#include <cuda_runtime.h>
#include <math.h>

#define NJ 17
#define ND 128
#define NH 2
#define NDH 64
#define NITER 4
#define LNEPS 1e-5f
#define NTHREADS 256
#define XSTR 20          // padded row stride for transposed xn tile (80B: 16B-aligned rows)

typedef unsigned long long ull;

// ---- fixed 17-node skeleton adjacency (incl. self), flattened neighbor lists ----
__constant__ int c_nbr_off[18] = {0,4,7,10,12,15,18,20,23,28,31,33,36,39,41,44,47,49};
__constant__ int c_nbr[49] = {
    0,1,4,7,  0,1,2,  1,2,3,  2,3,  0,4,5,  4,5,6,  5,6,  0,7,8,
    7,8,9,11,14,  8,9,10,  9,10,  8,11,12,  11,12,13,  12,13,
    8,14,15,  14,15,16,  15,16};

// Interleaved (w1,w2) pairs: g_w12[k*256+n] = (w1[k][n], w2[k][n]).
// SAME total bytes as the two separate streams (zip, not duplication) but the
// GEMM loop issues 1 LDG.64 instead of 2 LDG.32 per k.
__device__ float2 g_w12[ND * 2*ND];

__global__ void pack_weights_kernel(const float* __restrict__ w1,
                                    const float* __restrict__ w2) {
    const int i = blockIdx.x * blockDim.x + threadIdx.x;
    if (i < ND * 2*ND) g_w12[i] = make_float2(w1[i], w2[i]);
}

// float4/LDS.128 members must be 16B aligned (R1 lesson).
struct SmemLayout {
    alignas(16) float xs[NJ][ND];
    alignas(16) float x0s[NJ][ND];
    alignas(16) float xnT[ND][XSTR];   // row stride 80B (16-mult)
    alignas(16) float Ls[NJ][2*ND];
    alignas(16) float Rs[NJ][2*ND];
    alignas(16) float Vs[NJ][ND];
    alignas(16) float skipv[NJ];
    alignas(16) float lnG[ND];
    alignas(16) float lnB[ND];
    alignas(16) float aW[ND];
    alignas(16) float psW[ND];
    alignas(16) float vbs[ND];
    alignas(16) float b1s[2*ND];
    alignas(16) float b2s[2*ND];
    alignas(16) float alpha_b0;
    float ps_b0;
};

__device__ __forceinline__ float wredsum(float v) {
    #pragma unroll
    for (int o = 16; o; o >>= 1) v += __shfl_xor_sync(0xffffffffu, v, o);
    return v;
}

// ---- packed fp32x2 helpers (sm_103a FFMA2 path) ----
__device__ __forceinline__ void ffma2(ull& d, ull a, ull b) {
    asm("fma.rn.f32x2 %0, %1, %2, %0;" : "+l"(d) : "l"(a), "l"(b));
}
__device__ __forceinline__ ull pack2(float lo, float hi) {
    ull r; asm("mov.b64 %0, {%1, %2};" : "=l"(r) : "f"(lo), "f"(hi)); return r;
}
__device__ __forceinline__ float2 unpack2(ull v) {
    float lo, hi; asm("mov.b64 {%0, %1}, %2;" : "=f"(lo), "=f"(hi) : "l"(v));
    return make_float2(lo, hi);
}

__global__ void __launch_bounds__(NTHREADS, 2)
spatial_appnp_kernel(
    const float* __restrict__ x,
    const float* __restrict__ og,  const float* __restrict__ ob,
    const float* __restrict__ lg,  const float* __restrict__ lb,
    const float* __restrict__ aw,  const float* __restrict__ ab,
    const float* __restrict__ b1,  const float* __restrict__ b2,
    const float* __restrict__ psw, const float* __restrict__ psb,
    const float* __restrict__ vw,  const float* __restrict__ vb,
    float* __restrict__ out)
{
    extern __shared__ float smem_raw[];
    SmemLayout* sm = reinterpret_cast<SmemLayout*>(smem_raw);

    const int tid  = threadIdx.x;
    const int lane = tid & 31;
    const int wid  = tid >> 5;
    const int tile = blockIdx.x;
    const float* xg = x + (size_t)tile * NJ * ND;

    // ---- parameter staging (consumed after the first __syncthreads) ----
    for (int i = tid; i < ND; i += NTHREADS) {
        sm->lnG[i] = lg[i]; sm->lnB[i] = lb[i];
        sm->aW[i]  = aw[i]; sm->psW[i] = psw[i];
        sm->vbs[i] = vb[i];
    }
    for (int i = tid; i < 2*ND; i += NTHREADS) { sm->b1s[i] = b1[i]; sm->b2s[i] = b2[i]; }
    if (tid == 0) { sm->alpha_b0 = ab[0]; sm->ps_b0 = psb[0]; }

    // ---- outer LayerNorm: x -> xs, x0s (interleaved channels, one-pass var) ----
    for (int j = wid; j < NJ; j += 8) {
        const float v0 = xg[j*ND + lane];
        const float v1 = xg[j*ND + lane + 32];
        const float v2 = xg[j*ND + lane + 64];
        const float v3 = xg[j*ND + lane + 96];
        float s1 = v0+v1+v2+v3;
        float s2 = v0*v0+v1*v1+v2*v2+v3*v3;
        #pragma unroll
        for (int o = 16; o; o >>= 1) {
            s1 += __shfl_xor_sync(0xffffffffu, s1, o);
            s2 += __shfl_xor_sync(0xffffffffu, s2, o);
        }
        const float mean = s1 * (1.0f/ND);
        const float var  = s2 * (1.0f/ND) - mean*mean;
        const float rs = rsqrtf(var + LNEPS);
        const float y0 = (v0-mean)*rs*og[lane     ] + ob[lane     ];
        const float y1 = (v1-mean)*rs*og[lane + 32] + ob[lane + 32];
        const float y2 = (v2-mean)*rs*og[lane + 64] + ob[lane + 64];
        const float y3 = (v3-mean)*rs*og[lane + 96] + ob[lane + 96];
        sm->xs[j][lane     ] = y0;  sm->x0s[j][lane     ] = y0;
        sm->xs[j][lane + 32] = y1;  sm->x0s[j][lane + 32] = y1;
        sm->xs[j][lane + 64] = y2;  sm->x0s[j][lane + 64] = y2;
        sm->xs[j][lane + 96] = y3;  sm->x0s[j][lane + 96] = y3;
    }
    __syncthreads();

    for (int it = 0; it < NITER; ++it) {
        // ---- Phase 1: inner LN(xs) -> xnT (transposed), skip gate ----
        for (int j = wid; j < NJ; j += 8) {
            const float v0 = sm->xs[j][lane];
            const float v1 = sm->xs[j][lane + 32];
            const float v2 = sm->xs[j][lane + 64];
            const float v3 = sm->xs[j][lane + 96];
            float s1 = v0+v1+v2+v3;
            float s2 = v0*v0+v1*v1+v2*v2+v3*v3;
            #pragma unroll
            for (int o = 16; o; o >>= 1) {
                s1 += __shfl_xor_sync(0xffffffffu, s1, o);
                s2 += __shfl_xor_sync(0xffffffffu, s2, o);
            }
            const float mean = s1 * (1.0f/ND);
            const float var  = s2 * (1.0f/ND) - mean*mean;
            const float rs = rsqrtf(var + LNEPS);
            const float y0 = (v0-mean)*rs*sm->lnG[lane     ] + sm->lnB[lane     ];
            const float y1 = (v1-mean)*rs*sm->lnG[lane + 32] + sm->lnB[lane + 32];
            const float y2 = (v2-mean)*rs*sm->lnG[lane + 64] + sm->lnB[lane + 64];
            const float y3 = (v3-mean)*rs*sm->lnG[lane + 96] + sm->lnB[lane + 96];
            float dot = y0*sm->aW[lane] + y1*sm->aW[lane+32]
                      + y2*sm->aW[lane+64] + y3*sm->aW[lane+96];
            dot = wredsum(dot);
            if (lane == 0)
                sm->skipv[j] = 1.0f / (1.0f + expf(-(dot + sm->alpha_b0)));
            sm->xnT[lane     ][j] = y0;
            sm->xnT[lane + 32][j] = y1;
            sm->xnT[lane + 64][j] = y2;
            sm->xnT[lane + 96][j] = y3;
        }
        __syncthreads();

        // ---- Phase 2+3 fused: L = xn@w1+b1, R = xn@w2+b2, V = xn@v_w+v_b ----
        // (w1,w2) arrive as ONE interleaved LDG.64 per k (same bytes, fewer issues)
        {
            const int n  = tid;
            const int nv = tid & 127;
            ull accL[8], accR[8], accV[4];
            float aL16 = 0.f, aR16 = 0.f, aV16 = 0.f;
            #pragma unroll
            for (int q = 0; q < 8; ++q) { accL[q] = 0ull; accR[q] = 0ull; }
            #pragma unroll
            for (int q = 0; q < 4; ++q) accV[q] = 0ull;

            const ull* w12p = reinterpret_cast<const ull*>(g_w12) + n;
            const float* vwp = vw + nv;

            if (tid < 128) {
                #pragma unroll 4
                for (int k = 0; k < ND; ++k) {
                    const float2 wab = unpack2(w12p[k*(2*ND)]);
                    const float wv = vwp[k*ND];
                    const ull waa = pack2(wab.x, wab.x);
                    const ull wbb = pack2(wab.y, wab.y);
                    const ull wvv = pack2(wv, wv);
                    const ulonglong2* xr = reinterpret_cast<const ulonglong2*>(&sm->xnT[k][0]);
                    const ulonglong2 pA = xr[0];
                    const ulonglong2 pB = xr[1];
                    const ulonglong2 pC = xr[2];
                    const ulonglong2 pD = xr[3];
                    const float x16 = sm->xnT[k][16];
                    ffma2(accL[0], pA.x, waa); ffma2(accR[0], pA.x, wbb);
                    ffma2(accL[1], pA.y, waa); ffma2(accR[1], pA.y, wbb);
                    ffma2(accL[2], pB.x, waa); ffma2(accR[2], pB.x, wbb);
                    ffma2(accL[3], pB.y, waa); ffma2(accR[3], pB.y, wbb);
                    ffma2(accL[4], pC.x, waa); ffma2(accR[4], pC.x, wbb);
                    ffma2(accL[5], pC.y, waa); ffma2(accR[5], pC.y, wbb);
                    ffma2(accL[6], pD.x, waa); ffma2(accR[6], pD.x, wbb);
                    ffma2(accL[7], pD.y, waa); ffma2(accR[7], pD.y, wbb);
                    aL16 = fmaf(x16, wab.x, aL16);
                    aR16 = fmaf(x16, wab.y, aR16);
                    ffma2(accV[0], pA.x, wvv); ffma2(accV[1], pA.y, wvv);
                    ffma2(accV[2], pB.x, wvv); ffma2(accV[3], pB.y, wvv);
                    aV16 = fmaf(x16, wv, aV16);
                }
            } else {
                #pragma unroll 4
                for (int k = 0; k < ND; ++k) {
                    const float2 wab = unpack2(w12p[k*(2*ND)]);
                    const float wv = vwp[k*ND];
                    const ull waa = pack2(wab.x, wab.x);
                    const ull wbb = pack2(wab.y, wab.y);
                    const ull wvv = pack2(wv, wv);
                    const ulonglong2* xr = reinterpret_cast<const ulonglong2*>(&sm->xnT[k][0]);
                    const ulonglong2 pA = xr[0];
                    const ulonglong2 pB = xr[1];
                    const ulonglong2 pC = xr[2];
                    const ulonglong2 pD = xr[3];
                    const float x16 = sm->xnT[k][16];
                    ffma2(accL[0], pA.x, waa); ffma2(accR[0], pA.x, wbb);
                    ffma2(accL[1], pA.y, waa); ffma2(accR[1], pA.y, wbb);
                    ffma2(accL[2], pB.x, waa); ffma2(accR[2], pB.x, wbb);
                    ffma2(accL[3], pB.y, waa); ffma2(accR[3], pB.y, wbb);
                    ffma2(accL[4], pC.x, waa); ffma2(accR[4], pC.x, wbb);
                    ffma2(accL[5], pC.y, waa); ffma2(accR[5], pC.y, wbb);
                    ffma2(accL[6], pD.x, waa); ffma2(accR[6], pD.x, wbb);
                    ffma2(accL[7], pD.y, waa); ffma2(accR[7], pD.y, wbb);
                    aL16 = fmaf(x16, wab.x, aL16);
                    aR16 = fmaf(x16, wab.y, aR16);
                    ffma2(accV[0], pC.x, wvv); ffma2(accV[1], pC.y, wvv);
                    ffma2(accV[2], pD.x, wvv); ffma2(accV[3], pD.y, wvv);
                }
            }

            const float bb1 = sm->b1s[n], bb2 = sm->b2s[n];
            #pragma unroll
            for (int q = 0; q < 8; ++q) {
                const float2 l2 = unpack2(accL[q]);
                const float2 r2 = unpack2(accR[q]);
                sm->Ls[2*q  ][n] = l2.x + bb1;
                sm->Ls[2*q+1][n] = l2.y + bb1;
                sm->Rs[2*q  ][n] = r2.x + bb2;
                sm->Rs[2*q+1][n] = r2.y + bb2;
            }
            sm->Ls[16][n] = aL16 + bb1;
            sm->Rs[16][n] = aR16 + bb2;

            const float bbv = sm->vbs[nv];
            if (tid < 128) {
                #pragma unroll
                for (int q = 0; q < 4; ++q) {
                    const float2 v2 = unpack2(accV[q]);
                    sm->Vs[2*q  ][nv] = v2.x + bbv;
                    sm->Vs[2*q+1][nv] = v2.y + bbv;
                }
                sm->Vs[16][nv] = aV16 + bbv;
            } else {
                #pragma unroll
                for (int q = 0; q < 4; ++q) {
                    const float2 v2 = unpack2(accV[q]);
                    sm->Vs[8+2*q  ][nv] = v2.x + bbv;
                    sm->Vs[8+2*q+1][nv] = v2.y + bbv;
                }
            }
        }
        __syncthreads();

        // ---- Phase 4+5 fused: per-(h,i) edge scores + softmax + aggregate
        //      + gelu + skip combine -> xs ----
        for (int u = wid; u < 2*NJ; u += 8) {
            const int h  = (u >= NJ) ? 1 : 0;
            const int i  = u - h*NJ;
            const int o0 = c_nbr_off[i];
            const int deg = c_nbr_off[i+1] - o0;

            const float4 lv = reinterpret_cast<const float4*>(&sm->Ls[i][h*ND])[lane];
            const float4 pw = reinterpret_cast<const float4*>(sm->psW)[lane];

            float sc[5]; int nb[5];
            #pragma unroll
            for (int d = 0; d < 5; ++d) {
                const bool valid = d < deg;
                nb[d] = valid ? c_nbr[o0 + d] : i;
                const float4 rv = reinterpret_cast<const float4*>(&sm->Rs[nb[d]][h*ND])[lane];
                float z, acc;
                z = lv.x + rv.x; z = fmaxf(z, 0.2f*z); acc  = z*pw.x;
                z = lv.y + rv.y; z = fmaxf(z, 0.2f*z); acc += z*pw.y;
                z = lv.z + rv.z; z = fmaxf(z, 0.2f*z); acc += z*pw.z;
                z = lv.w + rv.w; z = fmaxf(z, 0.2f*z); acc += z*pw.w;
                sc[d] = acc;
            }
            // 5 interleaved warp reductions (chains overlap)
            #pragma unroll
            for (int o = 16; o; o >>= 1) {
                sc[0] += __shfl_xor_sync(0xffffffffu, sc[0], o);
                sc[1] += __shfl_xor_sync(0xffffffffu, sc[1], o);
                sc[2] += __shfl_xor_sync(0xffffffffu, sc[2], o);
                sc[3] += __shfl_xor_sync(0xffffffffu, sc[3], o);
                sc[4] += __shfl_xor_sync(0xffffffffu, sc[4], o);
            }
            const float psb0 = sm->ps_b0;
            #pragma unroll
            for (int d = 0; d < 5; ++d)
                sc[d] = (d < deg) ? sc[d] + psb0 : -1e30f;

            float m = sc[0];
            #pragma unroll
            for (int d = 1; d < 5; ++d) m = fmaxf(m, sc[d]);
            float den = 0.f;
            #pragma unroll
            for (int d = 0; d < 5; ++d) { sc[d] = expf(sc[d] - m); den += sc[d]; }
            const float inv = 1.0f / den;

            float acc0 = 0.f, acc1 = 0.f;
            #pragma unroll
            for (int d = 0; d < 5; ++d) {
                const float* vr = &sm->Vs[nb[d]][h*NDH];
                acc0 = fmaf(sc[d], vr[lane],      acc0);
                acc1 = fmaf(sc[d], vr[lane + 32], acc1);
            }
            acc0 *= inv; acc1 *= inv;
            acc0 = 0.5f*acc0*(1.0f + erff(acc0*0.70710678118654752f));
            acc1 = 0.5f*acc1*(1.0f + erff(acc1*0.70710678118654752f));
            const float sk = sm->skipv[i];
            const int c0 = h*NDH + lane;
            sm->xs[i][c0]      = (1.0f - sk)*acc0 + sk*sm->x0s[i][c0];
            sm->xs[i][c0+32]   = (1.0f - sk)*acc1 + sk*sm->x0s[i][c0+32];
        }
        __syncthreads();
    }

    // ---- write result ----
    float* og_out = out + (size_t)tile * NJ * ND;
    for (int j = wid; j < NJ; j += 8) {
        reinterpret_cast<float4*>(og_out + j*ND)[lane] =
            reinterpret_cast<const float4*>(sm->xs[j])[lane];
    }
}

extern "C" void kernel_launch(void* const* d_in, const int* in_sizes, int n_in,
                              void* d_out, int out_size) {
    const float* x   = (const float*)d_in[0];
    const float* og  = (const float*)d_in[1];
    const float* ob  = (const float*)d_in[2];
    const float* lg  = (const float*)d_in[3];
    const float* lb  = (const float*)d_in[4];
    const float* aw  = (const float*)d_in[5];
    const float* ab  = (const float*)d_in[6];
    const float* w1  = (const float*)d_in[7];
    const float* b1  = (const float*)d_in[8];
    const float* w2  = (const float*)d_in[9];
    const float* b2  = (const float*)d_in[10];
    const float* psw = (const float*)d_in[11];
    const float* psb = (const float*)d_in[12];
    const float* vw  = (const float*)d_in[13];
    const float* vb  = (const float*)d_in[14];

    const int tiles = in_sizes[0] / (NJ * ND);  // 3888

    // interleave (w1,w2) once per launch (same stream -> ordered)
    pack_weights_kernel<<<(ND*2*ND + 255)/256, 256>>>(w1, w2);

    const size_t smem_bytes = sizeof(SmemLayout);
    cudaFuncSetAttribute(spatial_appnp_kernel,
                         cudaFuncAttributeMaxDynamicSharedMemorySize,
                         (int)smem_bytes);
    spatial_appnp_kernel<<<tiles, NTHREADS, smem_bytes>>>(
        x, og, ob, lg, lb, aw, ab, b1, b2, psw, psb, vw, vb,
        (float*)d_out);
}

// round 12
// speedup vs baseline: 1.1845x; 1.0761x over previous
#include <cuda_runtime.h>
#include <math.h>

#define NJ 17
#define ND 128
#define NH 2
#define NDH 64
#define NITER 4
#define LNEPS 1e-5f
#define NTHREADS 256
#define XSTR 20          // padded row stride for transposed xn tile (80B: 16B-aligned rows)

typedef unsigned long long ull;

// ---- fixed 17-node skeleton adjacency (incl. self), flattened neighbor lists ----
__constant__ int c_nbr_off[18] = {0,4,7,10,12,15,18,20,23,28,31,33,36,39,41,44,47,49};
__constant__ int c_nbr[49] = {
    0,1,4,7,  0,1,2,  1,2,3,  2,3,  0,4,5,  4,5,6,  5,6,  0,7,8,
    7,8,9,11,14,  8,9,10,  9,10,  8,11,12,  11,12,13,  12,13,
    8,14,15,  14,15,16,  15,16};

// Interleaved (w1,w2) pairs: g_w12[k*256+n] = (w1[k][n], w2[k][n]).
// Same total bytes as two separate streams; 1 LDG.64 instead of 2 LDG.32 per k.
__device__ float2 g_w12[ND * 2*ND];

__global__ void pack_weights_kernel(const float* __restrict__ w1,
                                    const float* __restrict__ w2) {
    const int i = blockIdx.x * blockDim.x + threadIdx.x;
    if (i < ND * 2*ND) g_w12[i] = make_float2(w1[i], w2[i]);
}

// float4/LDS.128 members must be 16B aligned (R1 lesson).
struct SmemLayout {
    alignas(16) float x0s[NJ][ND];
    alignas(16) float xnT[ND][XSTR];   // row stride 80B (16-mult)
    alignas(16) float Ls[NJ][2*ND];
    alignas(16) float Rs[NJ][2*ND];
    alignas(16) float Vs[NJ][ND];
    alignas(16) float skipv[NJ];
    alignas(16) float lnG[ND];
    alignas(16) float lnB[ND];
    alignas(16) float aW[ND];
    alignas(16) float psW[ND];
    alignas(16) float vbs[ND];
    alignas(16) float b1s[2*ND];
    alignas(16) float b2s[2*ND];
    alignas(16) float alpha_b0;
    float ps_b0;
};

__device__ __forceinline__ float wredsum(float v) {
    #pragma unroll
    for (int o = 16; o; o >>= 1) v += __shfl_xor_sync(0xffffffffu, v, o);
    return v;
}

// ---- packed fp32x2 helpers (sm_103a FFMA2 path) ----
__device__ __forceinline__ void ffma2(ull& d, ull a, ull b) {
    asm("fma.rn.f32x2 %0, %1, %2, %0;" : "+l"(d) : "l"(a), "l"(b));
}
__device__ __forceinline__ ull pack2(float lo, float hi) {
    ull r; asm("mov.b64 %0, {%1, %2};" : "=l"(r) : "f"(lo), "f"(hi)); return r;
}
__device__ __forceinline__ float2 unpack2(ull v) {
    float lo, hi; asm("mov.b64 {%0, %1}, %2;" : "=f"(lo), "=f"(hi) : "l"(v));
    return make_float2(lo, hi);
}

__global__ void __launch_bounds__(NTHREADS, 2)
spatial_appnp_kernel(
    const float* __restrict__ x,
    const float* __restrict__ og,  const float* __restrict__ ob,
    const float* __restrict__ lg,  const float* __restrict__ lb,
    const float* __restrict__ aw,  const float* __restrict__ ab,
    const float* __restrict__ b1,  const float* __restrict__ b2,
    const float* __restrict__ psw, const float* __restrict__ psb,
    const float* __restrict__ vw,  const float* __restrict__ vb,
    float* __restrict__ out)
{
    extern __shared__ float smem_raw[];
    SmemLayout* sm = reinterpret_cast<SmemLayout*>(smem_raw);

    const int tid  = threadIdx.x;
    const int lane = tid & 31;
    const int wid  = tid >> 5;
    const int tile = blockIdx.x;
    const float* xg = x + (size_t)tile * NJ * ND;

    // ---- parameter staging ----
    for (int i = tid; i < ND; i += NTHREADS) {
        sm->lnG[i] = lg[i]; sm->lnB[i] = lb[i];
        sm->aW[i]  = aw[i]; sm->psW[i] = psw[i];
        sm->vbs[i] = vb[i];
    }
    for (int i = tid; i < 2*ND; i += NTHREADS) { sm->b1s[i] = b1[i]; sm->b2s[i] = b2[i]; }
    if (tid == 0) { sm->alpha_b0 = ab[0]; sm->ps_b0 = psb[0]; }
    __syncthreads();   // params visible to the fused prologue

    // ---- prologue: outer LN -> x0s, then inner LN in-regs -> xnT + skipv ----
    for (int j = wid; j < NJ; j += 8) {
        const float v0 = xg[j*ND + lane];
        const float v1 = xg[j*ND + lane + 32];
        const float v2 = xg[j*ND + lane + 64];
        const float v3 = xg[j*ND + lane + 96];
        float s1 = v0+v1+v2+v3;
        float s2 = v0*v0+v1*v1+v2*v2+v3*v3;
        #pragma unroll
        for (int o = 16; o; o >>= 1) {
            s1 += __shfl_xor_sync(0xffffffffu, s1, o);
            s2 += __shfl_xor_sync(0xffffffffu, s2, o);
        }
        const float mean = s1 * (1.0f/ND);
        const float var  = s2 * (1.0f/ND) - mean*mean;
        const float rs = rsqrtf(var + LNEPS);
        const float y0 = (v0-mean)*rs*og[lane     ] + ob[lane     ];
        const float y1 = (v1-mean)*rs*og[lane + 32] + ob[lane + 32];
        const float y2 = (v2-mean)*rs*og[lane + 64] + ob[lane + 64];
        const float y3 = (v3-mean)*rs*og[lane + 96] + ob[lane + 96];
        sm->x0s[j][lane     ] = y0;
        sm->x0s[j][lane + 32] = y1;
        sm->x0s[j][lane + 64] = y2;
        sm->x0s[j][lane + 96] = y3;

        // inner LN of y (first iteration's xn) without touching SMEM again
        float t1 = y0+y1+y2+y3;
        float t2 = y0*y0+y1*y1+y2*y2+y3*y3;
        #pragma unroll
        for (int o = 16; o; o >>= 1) {
            t1 += __shfl_xor_sync(0xffffffffu, t1, o);
            t2 += __shfl_xor_sync(0xffffffffu, t2, o);
        }
        const float mean2 = t1 * (1.0f/ND);
        const float var2  = t2 * (1.0f/ND) - mean2*mean2;
        const float rs2 = rsqrtf(var2 + LNEPS);
        const float z0 = (y0-mean2)*rs2*sm->lnG[lane     ] + sm->lnB[lane     ];
        const float z1 = (y1-mean2)*rs2*sm->lnG[lane + 32] + sm->lnB[lane + 32];
        const float z2 = (y2-mean2)*rs2*sm->lnG[lane + 64] + sm->lnB[lane + 64];
        const float z3 = (y3-mean2)*rs2*sm->lnG[lane + 96] + sm->lnB[lane + 96];
        float dot = z0*sm->aW[lane] + z1*sm->aW[lane+32]
                  + z2*sm->aW[lane+64] + z3*sm->aW[lane+96];
        dot = wredsum(dot);
        if (lane == 0)
            sm->skipv[j] = 1.0f / (1.0f + expf(-(dot + sm->alpha_b0)));
        sm->xnT[lane     ][j] = z0;
        sm->xnT[lane + 32][j] = z1;
        sm->xnT[lane + 64][j] = z2;
        sm->xnT[lane + 96][j] = z3;
    }

    float* og_out = out + (size_t)tile * NJ * ND;

    for (int it = 0; it < NITER; ++it) {
        __syncthreads();   // xnT ready / Ls,Rs protected from previous fused phase

        // ---- GEMM: L = xn@w1+b1, R = xn@w2+b2, V = xn@v_w+v_b (R9 champion) ----
        {
            const int n  = tid;
            const int nv = tid & 127;
            ull accL[8], accR[8], accV[4];
            float aL16 = 0.f, aR16 = 0.f, aV16 = 0.f;
            #pragma unroll
            for (int q = 0; q < 8; ++q) { accL[q] = 0ull; accR[q] = 0ull; }
            #pragma unroll
            for (int q = 0; q < 4; ++q) accV[q] = 0ull;

            const ull* w12p = reinterpret_cast<const ull*>(g_w12) + n;
            const float* vwp = vw + nv;

            if (tid < 128) {
                #pragma unroll 4
                for (int k = 0; k < ND; ++k) {
                    const float2 wab = unpack2(w12p[k*(2*ND)]);
                    const float wv = vwp[k*ND];
                    const ull waa = pack2(wab.x, wab.x);
                    const ull wbb = pack2(wab.y, wab.y);
                    const ull wvv = pack2(wv, wv);
                    const ulonglong2* xr = reinterpret_cast<const ulonglong2*>(&sm->xnT[k][0]);
                    const ulonglong2 pA = xr[0];
                    const ulonglong2 pB = xr[1];
                    const ulonglong2 pC = xr[2];
                    const ulonglong2 pD = xr[3];
                    const float x16 = sm->xnT[k][16];
                    ffma2(accL[0], pA.x, waa); ffma2(accR[0], pA.x, wbb);
                    ffma2(accL[1], pA.y, waa); ffma2(accR[1], pA.y, wbb);
                    ffma2(accL[2], pB.x, waa); ffma2(accR[2], pB.x, wbb);
                    ffma2(accL[3], pB.y, waa); ffma2(accR[3], pB.y, wbb);
                    ffma2(accL[4], pC.x, waa); ffma2(accR[4], pC.x, wbb);
                    ffma2(accL[5], pC.y, waa); ffma2(accR[5], pC.y, wbb);
                    ffma2(accL[6], pD.x, waa); ffma2(accR[6], pD.x, wbb);
                    ffma2(accL[7], pD.y, waa); ffma2(accR[7], pD.y, wbb);
                    aL16 = fmaf(x16, wab.x, aL16);
                    aR16 = fmaf(x16, wab.y, aR16);
                    ffma2(accV[0], pA.x, wvv); ffma2(accV[1], pA.y, wvv);
                    ffma2(accV[2], pB.x, wvv); ffma2(accV[3], pB.y, wvv);
                    aV16 = fmaf(x16, wv, aV16);
                }
            } else {
                #pragma unroll 4
                for (int k = 0; k < ND; ++k) {
                    const float2 wab = unpack2(w12p[k*(2*ND)]);
                    const float wv = vwp[k*ND];
                    const ull waa = pack2(wab.x, wab.x);
                    const ull wbb = pack2(wab.y, wab.y);
                    const ull wvv = pack2(wv, wv);
                    const ulonglong2* xr = reinterpret_cast<const ulonglong2*>(&sm->xnT[k][0]);
                    const ulonglong2 pA = xr[0];
                    const ulonglong2 pB = xr[1];
                    const ulonglong2 pC = xr[2];
                    const ulonglong2 pD = xr[3];
                    const float x16 = sm->xnT[k][16];
                    ffma2(accL[0], pA.x, waa); ffma2(accR[0], pA.x, wbb);
                    ffma2(accL[1], pA.y, waa); ffma2(accR[1], pA.y, wbb);
                    ffma2(accL[2], pB.x, waa); ffma2(accR[2], pB.x, wbb);
                    ffma2(accL[3], pB.y, waa); ffma2(accR[3], pB.y, wbb);
                    ffma2(accL[4], pC.x, waa); ffma2(accR[4], pC.x, wbb);
                    ffma2(accL[5], pC.y, waa); ffma2(accR[5], pC.y, wbb);
                    ffma2(accL[6], pD.x, waa); ffma2(accR[6], pD.x, wbb);
                    ffma2(accL[7], pD.y, waa); ffma2(accR[7], pD.y, wbb);
                    aL16 = fmaf(x16, wab.x, aL16);
                    aR16 = fmaf(x16, wab.y, aR16);
                    ffma2(accV[0], pC.x, wvv); ffma2(accV[1], pC.y, wvv);
                    ffma2(accV[2], pD.x, wvv); ffma2(accV[3], pD.y, wvv);
                }
            }

            const float bb1 = sm->b1s[n], bb2 = sm->b2s[n];
            #pragma unroll
            for (int q = 0; q < 8; ++q) {
                const float2 l2 = unpack2(accL[q]);
                const float2 r2 = unpack2(accR[q]);
                sm->Ls[2*q  ][n] = l2.x + bb1;
                sm->Ls[2*q+1][n] = l2.y + bb1;
                sm->Rs[2*q  ][n] = r2.x + bb2;
                sm->Rs[2*q+1][n] = r2.y + bb2;
            }
            sm->Ls[16][n] = aL16 + bb1;
            sm->Rs[16][n] = aR16 + bb2;

            const float bbv = sm->vbs[nv];
            if (tid < 128) {
                #pragma unroll
                for (int q = 0; q < 4; ++q) {
                    const float2 v2 = unpack2(accV[q]);
                    sm->Vs[2*q  ][nv] = v2.x + bbv;
                    sm->Vs[2*q+1][nv] = v2.y + bbv;
                }
                sm->Vs[16][nv] = aV16 + bbv;
            } else {
                #pragma unroll
                for (int q = 0; q < 4; ++q) {
                    const float2 v2 = unpack2(accV[q]);
                    sm->Vs[8+2*q  ][nv] = v2.x + bbv;
                    sm->Vs[8+2*q+1][nv] = v2.y + bbv;
                }
            }
        }
        __syncthreads();   // L/R/V ready

        // ---- fused: both-head attention + gelu + skip, then next-iter LN+xnT
        //      (or final global write on the last iteration) ----
        for (int i = wid; i < NJ; i += 8) {
            const int o0 = c_nbr_off[i];
            const int deg = c_nbr_off[i+1] - o0;

            const float4 lv0 = reinterpret_cast<const float4*>(&sm->Ls[i][0 ])[lane];
            const float4 lv1 = reinterpret_cast<const float4*>(&sm->Ls[i][ND])[lane];
            const float4 pw  = reinterpret_cast<const float4*>(sm->psW)[lane];

            float sc0[5], sc1[5]; int nb[5];
            #pragma unroll
            for (int d = 0; d < 5; ++d) {
                nb[d] = (d < deg) ? c_nbr[o0 + d] : i;
                const float4 rv0 = reinterpret_cast<const float4*>(&sm->Rs[nb[d]][0 ])[lane];
                const float4 rv1 = reinterpret_cast<const float4*>(&sm->Rs[nb[d]][ND])[lane];
                float z, a0, a1;
                z = lv0.x + rv0.x; z = fmaxf(z, 0.2f*z); a0  = z*pw.x;
                z = lv0.y + rv0.y; z = fmaxf(z, 0.2f*z); a0 += z*pw.y;
                z = lv0.z + rv0.z; z = fmaxf(z, 0.2f*z); a0 += z*pw.z;
                z = lv0.w + rv0.w; z = fmaxf(z, 0.2f*z); a0 += z*pw.w;
                z = lv1.x + rv1.x; z = fmaxf(z, 0.2f*z); a1  = z*pw.x;
                z = lv1.y + rv1.y; z = fmaxf(z, 0.2f*z); a1 += z*pw.y;
                z = lv1.z + rv1.z; z = fmaxf(z, 0.2f*z); a1 += z*pw.z;
                z = lv1.w + rv1.w; z = fmaxf(z, 0.2f*z); a1 += z*pw.w;
                sc0[d] = a0; sc1[d] = a1;
            }
            // 10 interleaved warp reductions (chains overlap)
            #pragma unroll
            for (int o = 16; o; o >>= 1) {
                sc0[0] += __shfl_xor_sync(0xffffffffu, sc0[0], o);
                sc0[1] += __shfl_xor_sync(0xffffffffu, sc0[1], o);
                sc0[2] += __shfl_xor_sync(0xffffffffu, sc0[2], o);
                sc0[3] += __shfl_xor_sync(0xffffffffu, sc0[3], o);
                sc0[4] += __shfl_xor_sync(0xffffffffu, sc0[4], o);
                sc1[0] += __shfl_xor_sync(0xffffffffu, sc1[0], o);
                sc1[1] += __shfl_xor_sync(0xffffffffu, sc1[1], o);
                sc1[2] += __shfl_xor_sync(0xffffffffu, sc1[2], o);
                sc1[3] += __shfl_xor_sync(0xffffffffu, sc1[3], o);
                sc1[4] += __shfl_xor_sync(0xffffffffu, sc1[4], o);
            }
            const float psb0 = sm->ps_b0;
            #pragma unroll
            for (int d = 0; d < 5; ++d) {
                sc0[d] = (d < deg) ? sc0[d] + psb0 : -1e30f;
                sc1[d] = (d < deg) ? sc1[d] + psb0 : -1e30f;
            }

            float m0 = sc0[0], m1 = sc1[0];
            #pragma unroll
            for (int d = 1; d < 5; ++d) { m0 = fmaxf(m0, sc0[d]); m1 = fmaxf(m1, sc1[d]); }
            float den0 = 0.f, den1 = 0.f;
            #pragma unroll
            for (int d = 0; d < 5; ++d) {
                sc0[d] = expf(sc0[d] - m0); den0 += sc0[d];
                sc1[d] = expf(sc1[d] - m1); den1 += sc1[d];
            }
            const float inv0 = 1.0f / den0;
            const float inv1 = 1.0f / den1;

            float a0 = 0.f, a1 = 0.f, a2 = 0.f, a3 = 0.f;
            #pragma unroll
            for (int d = 0; d < 5; ++d) {
                const float* vr = sm->Vs[nb[d]];
                a0 = fmaf(sc0[d], vr[lane     ], a0);
                a1 = fmaf(sc0[d], vr[lane + 32], a1);
                a2 = fmaf(sc1[d], vr[lane + 64], a2);
                a3 = fmaf(sc1[d], vr[lane + 96], a3);
            }
            a0 *= inv0; a1 *= inv0; a2 *= inv1; a3 *= inv1;
            a0 = 0.5f*a0*(1.0f + erff(a0*0.70710678118654752f));
            a1 = 0.5f*a1*(1.0f + erff(a1*0.70710678118654752f));
            a2 = 0.5f*a2*(1.0f + erff(a2*0.70710678118654752f));
            a3 = 0.5f*a3*(1.0f + erff(a3*0.70710678118654752f));

            const float sk = sm->skipv[i];
            const float y0 = (1.0f - sk)*a0 + sk*sm->x0s[i][lane     ];
            const float y1 = (1.0f - sk)*a1 + sk*sm->x0s[i][lane + 32];
            const float y2 = (1.0f - sk)*a2 + sk*sm->x0s[i][lane + 64];
            const float y3 = (1.0f - sk)*a3 + sk*sm->x0s[i][lane + 96];

            if (it < NITER-1) {
                // next iteration's inner LN + transpose, entirely in-warp
                float s1 = y0+y1+y2+y3;
                float s2 = y0*y0+y1*y1+y2*y2+y3*y3;
                #pragma unroll
                for (int o = 16; o; o >>= 1) {
                    s1 += __shfl_xor_sync(0xffffffffu, s1, o);
                    s2 += __shfl_xor_sync(0xffffffffu, s2, o);
                }
                const float mean = s1 * (1.0f/ND);
                const float var  = s2 * (1.0f/ND) - mean*mean;
                const float rs = rsqrtf(var + LNEPS);
                const float z0 = (y0-mean)*rs*sm->lnG[lane     ] + sm->lnB[lane     ];
                const float z1 = (y1-mean)*rs*sm->lnG[lane + 32] + sm->lnB[lane + 32];
                const float z2 = (y2-mean)*rs*sm->lnG[lane + 64] + sm->lnB[lane + 64];
                const float z3 = (y3-mean)*rs*sm->lnG[lane + 96] + sm->lnB[lane + 96];
                float dot = z0*sm->aW[lane] + z1*sm->aW[lane+32]
                          + z2*sm->aW[lane+64] + z3*sm->aW[lane+96];
                dot = wredsum(dot);
                if (lane == 0)
                    sm->skipv[i] = 1.0f / (1.0f + expf(-(dot + sm->alpha_b0)));
                sm->xnT[lane     ][i] = z0;
                sm->xnT[lane + 32][i] = z1;
                sm->xnT[lane + 64][i] = z2;
                sm->xnT[lane + 96][i] = z3;
            } else {
                og_out[i*ND + lane     ] = y0;
                og_out[i*ND + lane + 32] = y1;
                og_out[i*ND + lane + 64] = y2;
                og_out[i*ND + lane + 96] = y3;
            }
        }
    }
}

extern "C" void kernel_launch(void* const* d_in, const int* in_sizes, int n_in,
                              void* d_out, int out_size) {
    const float* x   = (const float*)d_in[0];
    const float* og  = (const float*)d_in[1];
    const float* ob  = (const float*)d_in[2];
    const float* lg  = (const float*)d_in[3];
    const float* lb  = (const float*)d_in[4];
    const float* aw  = (const float*)d_in[5];
    const float* ab  = (const float*)d_in[6];
    const float* w1  = (const float*)d_in[7];
    const float* b1  = (const float*)d_in[8];
    const float* w2  = (const float*)d_in[9];
    const float* b2  = (const float*)d_in[10];
    const float* psw = (const float*)d_in[11];
    const float* psb = (const float*)d_in[12];
    const float* vw  = (const float*)d_in[13];
    const float* vb  = (const float*)d_in[14];

    const int tiles = in_sizes[0] / (NJ * ND);  // 3888

    // interleave (w1,w2) once per launch (same stream -> ordered)
    pack_weights_kernel<<<(ND*2*ND + 255)/256, 256>>>(w1, w2);

    const size_t smem_bytes = sizeof(SmemLayout);
    cudaFuncSetAttribute(spatial_appnp_kernel,
                         cudaFuncAttributeMaxDynamicSharedMemorySize,
                         (int)smem_bytes);
    spatial_appnp_kernel<<<tiles, NTHREADS, smem_bytes>>>(
        x, og, ob, lg, lb, aw, ab, b1, b2, psw, psb, vw, vb,
        (float*)d_out);
}